// round 2
// baseline (speedup 1.0000x reference)
#include <cuda_runtime.h>
#include <cuda_fp16.h>
#include <cstdint>
#include <math.h>

// Problem constants
#define B_  2
#define Q_  2048
#define KV_ 2048
#define D_  1024
#define H_  16
#define DH_ 64

// ---------------------------------------------------------------------------
// Scratch (device globals — allocation-free per harness rules)
// ---------------------------------------------------------------------------
__device__ float  g_qn[B_ * Q_ * D_];        // 16.8 MB  rmsnorm(query)
__device__ float  g_kn[B_ * KV_ * D_];       // 16.8 MB  rmsnorm(key)
__device__ float  g_qp[B_ * Q_ * D_];        // 16.8 MB  q projection
__device__ float  g_kp[B_ * KV_ * D_];       // 16.8 MB  k projection
__device__ float  g_attn[B_ * Q_ * KV_];     // 33.6 MB  head-averaged probs
__device__ __half g_scores[134217728];       // 268 MB   per-head scores [B,H,Q,KV] fp16

// ---------------------------------------------------------------------------
// Helpers
// ---------------------------------------------------------------------------
__device__ __forceinline__ uint32_t f2tf(float x) {
    uint32_t r;
    asm("cvt.rna.tf32.f32 %0, %1;" : "=r"(r) : "f"(x));
    return r;
}

__device__ __forceinline__ void mma8(float* d, const uint32_t* a, const uint32_t* b) {
    asm volatile(
        "mma.sync.aligned.m16n8k8.row.col.f32.tf32.tf32.f32 "
        "{%0,%1,%2,%3}, {%4,%5,%6,%7}, {%8,%9}, {%0,%1,%2,%3};\n"
        : "+f"(d[0]), "+f"(d[1]), "+f"(d[2]), "+f"(d[3])
        : "r"(a[0]), "r"(a[1]), "r"(a[2]), "r"(a[3]), "r"(b[0]), "r"(b[1]));
}

// ---------------------------------------------------------------------------
// Kernel 1: RMSNorm for query (rows [0,4096)) and key (rows [4096,8192))
// One block per row of 1024, 256 threads (1 float4 per thread).
// ---------------------------------------------------------------------------
__global__ __launch_bounds__(256) void rmsnorm_kernel(
    const float* __restrict__ q, const float* __restrict__ k,
    const float* __restrict__ wq, const float* __restrict__ wk)
{
    __shared__ float red[8];
    int row = blockIdx.x;
    int tid = threadIdx.x;

    const float* x;
    const float* w;
    float* y;
    if (row < B_ * Q_) {
        x = q + (size_t)row * D_;  w = wq;  y = g_qn + (size_t)row * D_;
    } else {
        int r2 = row - B_ * Q_;
        x = k + (size_t)r2 * D_;   w = wk;  y = g_kn + (size_t)r2 * D_;
    }

    float4 v = ((const float4*)x)[tid];
    float ss = v.x * v.x + v.y * v.y + v.z * v.z + v.w * v.w;
#pragma unroll
    for (int o = 16; o; o >>= 1) ss += __shfl_xor_sync(0xffffffffu, ss, o);
    if ((tid & 31) == 0) red[tid >> 5] = ss;
    __syncthreads();
    if (tid < 32) {
        float s2 = (tid < 8) ? red[tid] : 0.0f;
#pragma unroll
        for (int o = 4; o; o >>= 1) s2 += __shfl_xor_sync(0xffffffffu, s2, o);
        if (tid == 0) red[0] = s2;
    }
    __syncthreads();

    // jnp.finfo(float32).eps
    float scale = rsqrtf(red[0] * (1.0f / (float)D_) + 1.1920928955078125e-07f);
    float4 wv = ((const float4*)w)[tid];
    float4 out;
    out.x = v.x * scale * wv.x;
    out.y = v.y * scale * wv.y;
    out.z = v.z * scale * wv.z;
    out.w = v.w * scale * wv.w;
    ((float4*)y)[tid] = out;
}

// ---------------------------------------------------------------------------
// GEMM (NT): C = A @ B^T + bias, fp32 out. A[M,K] rm, B[N,K] rm.
// TF32 mma.sync m16n8k8, fp32 accumulate. 128x128 tile, BK=32, 8 warps.
// Used for the two projections.
// ---------------------------------------------------------------------------
#define BM 128
#define BN 128
#define BK 32

__global__ __launch_bounds__(256) void gemm_nt_kernel(
    const float* __restrict__ A, const float* __restrict__ Bp, float* __restrict__ C,
    int lda, int ldb, int ldc, const float* __restrict__ bias)
{
    __shared__ uint32_t As[BM][BK + 4];
    __shared__ uint32_t Bs[BN][BK + 4];

    int bm = blockIdx.y * BM;
    int bn = blockIdx.x * BN;
    int tid = threadIdx.x, lane = tid & 31, wid = tid >> 5;
    int wm = (wid >> 2) * 64;   // 2 warp rows
    int wn = (wid & 3) * 32;    // 4 warp cols

    float acc[4][4][4];
#pragma unroll
    for (int mi = 0; mi < 4; mi++)
#pragma unroll
        for (int ni = 0; ni < 4; ni++)
#pragma unroll
            for (int c = 0; c < 4; c++) acc[mi][ni][c] = 0.0f;

    for (int kt = 0; kt < D_; kt += BK) {
#pragma unroll
        for (int i = 0; i < 4; i++) {
            int f  = tid + i * 256;        // float4 index in [0,1024)
            int r  = f >> 3;               // 8 float4 per 32-float row
            int c4 = (f & 7) << 2;
            float4 va = *(const float4*)(A + (size_t)(bm + r) * lda + kt + c4);
            As[r][c4]     = f2tf(va.x);
            As[r][c4 + 1] = f2tf(va.y);
            As[r][c4 + 2] = f2tf(va.z);
            As[r][c4 + 3] = f2tf(va.w);
            float4 vb = *(const float4*)(Bp + (size_t)(bn + r) * ldb + kt + c4);
            Bs[r][c4]     = f2tf(vb.x);
            Bs[r][c4 + 1] = f2tf(vb.y);
            Bs[r][c4 + 2] = f2tf(vb.z);
            Bs[r][c4 + 3] = f2tf(vb.w);
        }
        __syncthreads();

#pragma unroll
        for (int kk = 0; kk < BK; kk += 8) {
            uint32_t af[4][4], bf[4][2];
#pragma unroll
            for (int mi = 0; mi < 4; mi++) {
                int r0 = wm + mi * 16 + (lane >> 2);
                int c0 = kk + (lane & 3);
                af[mi][0] = As[r0][c0];
                af[mi][1] = As[r0 + 8][c0];
                af[mi][2] = As[r0][c0 + 4];
                af[mi][3] = As[r0 + 8][c0 + 4];
            }
#pragma unroll
            for (int ni = 0; ni < 4; ni++) {
                int n0 = wn + ni * 8 + (lane >> 2);
                int c0 = kk + (lane & 3);
                bf[ni][0] = Bs[n0][c0];
                bf[ni][1] = Bs[n0][c0 + 4];
            }
#pragma unroll
            for (int mi = 0; mi < 4; mi++)
#pragma unroll
                for (int ni = 0; ni < 4; ni++)
                    mma8(acc[mi][ni], af[mi], bf[ni]);
        }
        __syncthreads();
    }

#pragma unroll
    for (int mi = 0; mi < 4; mi++) {
        int r0 = bm + wm + mi * 16 + (lane >> 2);
#pragma unroll
        for (int ni = 0; ni < 4; ni++) {
            int c0 = bn + wn + ni * 8 + ((lane & 3) << 1);
            float b0 = bias[c0], b1 = bias[c0 + 1];
            C[(size_t)r0 * ldc + c0]           = acc[mi][ni][0] + b0;
            C[(size_t)r0 * ldc + c0 + 1]       = acc[mi][ni][1] + b1;
            C[(size_t)(r0 + 8) * ldc + c0]     = acc[mi][ni][2] + b0;
            C[(size_t)(r0 + 8) * ldc + c0 + 1] = acc[mi][ni][3] + b1;
        }
    }
}

// ---------------------------------------------------------------------------
// Scores GEMM (NT, batched over B*H): S = (1/8) qp_h @ kp_h^T -> fp16 out.
// K = 64 (one head slice), strided through the D=1024 projection rows.
// ---------------------------------------------------------------------------
__global__ __launch_bounds__(256) void gemm_scores_kernel(
    const float* __restrict__ QP, const float* __restrict__ KP, __half* __restrict__ S)
{
    __shared__ uint32_t As[BM][BK + 4];
    __shared__ uint32_t Bs[BN][BK + 4];

    int z  = blockIdx.z;               // b*H + h
    int bb = z >> 4;
    int hh = z & 15;
    const float* A  = QP + (size_t)bb * Q_ * D_  + hh * DH_;
    const float* Bp = KP + (size_t)bb * KV_ * D_ + hh * DH_;
    __half*      C  = S  + (size_t)z * Q_ * KV_;

    int bm = blockIdx.y * BM;
    int bn = blockIdx.x * BN;
    int tid = threadIdx.x, lane = tid & 31, wid = tid >> 5;
    int wm = (wid >> 2) * 64;
    int wn = (wid & 3) * 32;

    float acc[4][4][4];
#pragma unroll
    for (int mi = 0; mi < 4; mi++)
#pragma unroll
        for (int ni = 0; ni < 4; ni++)
#pragma unroll
            for (int c = 0; c < 4; c++) acc[mi][ni][c] = 0.0f;

#pragma unroll
    for (int kt = 0; kt < DH_; kt += BK) {
#pragma unroll
        for (int i = 0; i < 4; i++) {
            int f  = tid + i * 256;
            int r  = f >> 3;
            int c4 = (f & 7) << 2;
            float4 va = *(const float4*)(A + (size_t)(bm + r) * D_ + kt + c4);
            As[r][c4]     = f2tf(va.x);
            As[r][c4 + 1] = f2tf(va.y);
            As[r][c4 + 2] = f2tf(va.z);
            As[r][c4 + 3] = f2tf(va.w);
            float4 vb = *(const float4*)(Bp + (size_t)(bn + r) * D_ + kt + c4);
            Bs[r][c4]     = f2tf(vb.x);
            Bs[r][c4 + 1] = f2tf(vb.y);
            Bs[r][c4 + 2] = f2tf(vb.z);
            Bs[r][c4 + 3] = f2tf(vb.w);
        }
        __syncthreads();

#pragma unroll
        for (int kk = 0; kk < BK; kk += 8) {
            uint32_t af[4][4], bf[4][2];
#pragma unroll
            for (int mi = 0; mi < 4; mi++) {
                int r0 = wm + mi * 16 + (lane >> 2);
                int c0 = kk + (lane & 3);
                af[mi][0] = As[r0][c0];
                af[mi][1] = As[r0 + 8][c0];
                af[mi][2] = As[r0][c0 + 4];
                af[mi][3] = As[r0 + 8][c0 + 4];
            }
#pragma unroll
            for (int ni = 0; ni < 4; ni++) {
                int n0 = wn + ni * 8 + (lane >> 2);
                int c0 = kk + (lane & 3);
                bf[ni][0] = Bs[n0][c0];
                bf[ni][1] = Bs[n0][c0 + 4];
            }
#pragma unroll
            for (int mi = 0; mi < 4; mi++)
#pragma unroll
                for (int ni = 0; ni < 4; ni++)
                    mma8(acc[mi][ni], af[mi], bf[ni]);
        }
        __syncthreads();
    }

#pragma unroll
    for (int mi = 0; mi < 4; mi++) {
        int r0 = bm + wm + mi * 16 + (lane >> 2);
#pragma unroll
        for (int ni = 0; ni < 4; ni++) {
            int c0 = bn + wn + ni * 8 + ((lane & 3) << 1);
            __half2 h0 = __floats2half2_rn(acc[mi][ni][0] * 0.125f, acc[mi][ni][1] * 0.125f);
            __half2 h1 = __floats2half2_rn(acc[mi][ni][2] * 0.125f, acc[mi][ni][3] * 0.125f);
            *(__half2*)(C + (size_t)r0 * KV_ + c0)       = h0;
            *(__half2*)(C + (size_t)(r0 + 8) * KV_ + c0) = h1;
        }
    }
}

// ---------------------------------------------------------------------------
// GEMM (NN): C = A @ B, A[M,K] rm, B[K,N] rm. Batched over z (batch b).
// Used for: features = attn @ value (writes d_out directly).
// ---------------------------------------------------------------------------
__global__ __launch_bounds__(256) void gemm_nn_kernel(
    const float* __restrict__ A0, const float* __restrict__ B0, float* __restrict__ C0)
{
    __shared__ uint32_t As[BM][BK + 4];
    __shared__ uint32_t Bs[BK][BN + 8];

    int z = blockIdx.z;
    const float* A  = A0 + (size_t)z * Q_ * KV_;
    const float* Bp = B0 + (size_t)z * KV_ * D_;
    float*       C  = C0 + (size_t)z * Q_ * D_;

    int bm = blockIdx.y * BM;
    int bn = blockIdx.x * BN;
    int tid = threadIdx.x, lane = tid & 31, wid = tid >> 5;
    int wm = (wid >> 2) * 64;
    int wn = (wid & 3) * 32;

    float acc[4][4][4];
#pragma unroll
    for (int mi = 0; mi < 4; mi++)
#pragma unroll
        for (int ni = 0; ni < 4; ni++)
#pragma unroll
            for (int c = 0; c < 4; c++) acc[mi][ni][c] = 0.0f;

    for (int kt = 0; kt < KV_; kt += BK) {
#pragma unroll
        for (int i = 0; i < 4; i++) {
            int f  = tid + i * 256;
            int ra  = f >> 3;
            int ca4 = (f & 7) << 2;
            float4 va = *(const float4*)(A + (size_t)(bm + ra) * KV_ + kt + ca4);
            As[ra][ca4]     = f2tf(va.x);
            As[ra][ca4 + 1] = f2tf(va.y);
            As[ra][ca4 + 2] = f2tf(va.z);
            As[ra][ca4 + 3] = f2tf(va.w);
            int rb  = f >> 5;
            int cb4 = (f & 31) << 2;
            float4 vb = *(const float4*)(Bp + (size_t)(kt + rb) * D_ + bn + cb4);
            Bs[rb][cb4]     = f2tf(vb.x);
            Bs[rb][cb4 + 1] = f2tf(vb.y);
            Bs[rb][cb4 + 2] = f2tf(vb.z);
            Bs[rb][cb4 + 3] = f2tf(vb.w);
        }
        __syncthreads();

#pragma unroll
        for (int kk = 0; kk < BK; kk += 8) {
            uint32_t af[4][4], bf[4][2];
#pragma unroll
            for (int mi = 0; mi < 4; mi++) {
                int r0 = wm + mi * 16 + (lane >> 2);
                int c0 = kk + (lane & 3);
                af[mi][0] = As[r0][c0];
                af[mi][1] = As[r0 + 8][c0];
                af[mi][2] = As[r0][c0 + 4];
                af[mi][3] = As[r0 + 8][c0 + 4];
            }
#pragma unroll
            for (int ni = 0; ni < 4; ni++) {
                int n0 = wn + ni * 8 + (lane >> 2);
                int k0 = kk + (lane & 3);
                bf[ni][0] = Bs[k0][n0];
                bf[ni][1] = Bs[k0 + 4][n0];
            }
#pragma unroll
            for (int mi = 0; mi < 4; mi++)
#pragma unroll
                for (int ni = 0; ni < 4; ni++)
                    mma8(acc[mi][ni], af[mi], bf[ni]);
        }
        __syncthreads();
    }

#pragma unroll
    for (int mi = 0; mi < 4; mi++) {
        int r0 = bm + wm + mi * 16 + (lane >> 2);
#pragma unroll
        for (int ni = 0; ni < 4; ni++) {
            int c0 = bn + wn + ni * 8 + ((lane & 3) << 1);
            C[(size_t)r0 * D_ + c0]           = acc[mi][ni][0];
            C[(size_t)r0 * D_ + c0 + 1]       = acc[mi][ni][1];
            C[(size_t)(r0 + 8) * D_ + c0]     = acc[mi][ni][2];
            C[(size_t)(r0 + 8) * D_ + c0 + 1] = acc[mi][ni][3];
        }
    }
}

// ---------------------------------------------------------------------------
// Kernel: per-(b,q-row) softmax over KV for each head, averaged over heads.
// One block per (b,i); 256 threads hold the 2048-wide fp16 row (8/thread).
// ---------------------------------------------------------------------------
__global__ __launch_bounds__(256) void softmax_avg_kernel() {
    __shared__ float red[8];
    int tid = threadIdx.x;
    int bi  = blockIdx.x;
    int b   = bi >> 11;        // /2048
    int i   = bi & 2047;

    float accv[8];
#pragma unroll
    for (int c = 0; c < 8; c++) accv[c] = 0.0f;

    for (int h = 0; h < H_; h++) {
        const __half* srow = g_scores + (size_t)(b * H_ + h) * Q_ * KV_ + (size_t)i * KV_;
        // 8 halves per thread as one 16-byte load
        float v[8];
        {
            uint4 raw = ((const uint4*)srow)[tid];
            __half2* hp = (__half2*)&raw;
#pragma unroll
            for (int c = 0; c < 4; c++) {
                float2 f2 = __half22float2(hp[c]);
                v[2 * c] = f2.x;
                v[2 * c + 1] = f2.y;
            }
        }

        float m = v[0];
#pragma unroll
        for (int c = 1; c < 8; c++) m = fmaxf(m, v[c]);
#pragma unroll
        for (int o = 16; o; o >>= 1) m = fmaxf(m, __shfl_xor_sync(0xffffffffu, m, o));
        if ((tid & 31) == 0) red[tid >> 5] = m;
        __syncthreads();
        if (tid < 32) {
            float mm = (tid < 8) ? red[tid] : -3.402823466e38f;
#pragma unroll
            for (int o = 4; o; o >>= 1) mm = fmaxf(mm, __shfl_xor_sync(0xffffffffu, mm, o));
            if (tid == 0) red[0] = mm;
        }
        __syncthreads();
        m = red[0];
        __syncthreads();

        float e[8];
#pragma unroll
        for (int c = 0; c < 8; c++) e[c] = __expf(v[c] - m);

        float s = e[0] + e[1] + e[2] + e[3] + e[4] + e[5] + e[6] + e[7];
#pragma unroll
        for (int o = 16; o; o >>= 1) s += __shfl_xor_sync(0xffffffffu, s, o);
        if ((tid & 31) == 0) red[tid >> 5] = s;
        __syncthreads();
        if (tid < 32) {
            float s2 = (tid < 8) ? red[tid] : 0.0f;
#pragma unroll
            for (int o = 4; o; o >>= 1) s2 += __shfl_xor_sync(0xffffffffu, s2, o);
            if (tid == 0) red[0] = s2;
        }
        __syncthreads();
        s = red[0];
        __syncthreads();

        float inv = 1.0f / ((float)H_ * s);
#pragma unroll
        for (int c2 = 0; c2 < 8; c2++) accv[c2] += e[c2] * inv;
    }

    float* arow = g_attn + ((size_t)b * Q_ + i) * KV_;
    ((float4*)arow)[2 * tid]     = make_float4(accv[0], accv[1], accv[2], accv[3]);
    ((float4*)arow)[2 * tid + 1] = make_float4(accv[4], accv[5], accv[6], accv[7]);
}

// ---------------------------------------------------------------------------
// Host launcher
// ---------------------------------------------------------------------------
extern "C" void kernel_launch(void* const* d_in, const int* in_sizes, int n_in,
                              void* d_out, int out_size)
{
    (void)in_sizes; (void)n_in; (void)out_size;
    const float* query = (const float*)d_in[0];
    const float* key   = (const float*)d_in[1];
    const float* value = (const float*)d_in[2];
    const float* wqn   = (const float*)d_in[3];
    const float* wkn   = (const float*)d_in[4];
    const float* Wq    = (const float*)d_in[5];
    const float* Wk    = (const float*)d_in[6];
    const float* bq    = (const float*)d_in[7];
    const float* bk    = (const float*)d_in[8];
    float* out = (float*)d_out;

    float *qn, *kn, *qp, *kp, *attn;
    __half* sc;
    cudaGetSymbolAddress((void**)&qn,   g_qn);
    cudaGetSymbolAddress((void**)&kn,   g_kn);
    cudaGetSymbolAddress((void**)&qp,   g_qp);
    cudaGetSymbolAddress((void**)&kp,   g_kp);
    cudaGetSymbolAddress((void**)&attn, g_attn);
    cudaGetSymbolAddress((void**)&sc,   g_scores);

    // 1) RMSNorm for q (4096 rows) and k (4096 rows)
    rmsnorm_kernel<<<B_ * Q_ + B_ * KV_, 256>>>(query, key, wqn, wkn);

    // 2) Projections: qp = qn @ Wq^T + bq ; kp = kn @ Wk^T + bk
    dim3 gproj(D_ / BN, (B_ * Q_) / BM, 1);   // (8, 32, 1)
    gemm_nt_kernel<<<gproj, 256>>>(qn, Wq, qp, D_, D_, D_, bq);
    gemm_nt_kernel<<<gproj, 256>>>(kn, Wk, kp, D_, D_, D_, bk);

    // 3) Scores: S[b,h,i,j] = (1/8) * qp[b,i,h*64:] . kp[b,j,h*64:]  (fp16)
    dim3 gsc(KV_ / BN, Q_ / BM, B_ * H_);     // (16, 16, 32)
    gemm_scores_kernel<<<gsc, 256>>>(qp, kp, sc);

    // 4) Softmax over KV per head, averaged over heads -> g_attn (fp32)
    softmax_avg_kernel<<<B_ * Q_, 256>>>();

    // 5) features = attn @ value  -> d_out
    dim3 gpv(D_ / BN, Q_ / BM, B_);           // (8, 16, 2)
    gemm_nn_kernel<<<gpv, 256>>>(attn, value, out);
}